// round 17
// baseline (speedup 1.0000x reference)
#include <cuda_runtime.h>
#include <cuda_fp16.h>

// GCN symmetric-normalized CSR aggregation, two-phase:
//   Phase 1: norm_feat[s,:] = (half) rsqrt(deg[s]) * feat[s,:]
//            (+ zero row at MAX_NODES as padding gather target).
//   Phase 2: out[d,:] = rsqrt(deg[d]) * sum_{e in row d} norm_feat[col[e],:]
//
// Phase 2 (R12 structure): one warp per 4 consecutive destination nodes,
// sequential. 16 lanes cover a 128B fp16 row (8B/lane); each LDG.64 gathers
// two edges (one per half-warp). col_idx read directly with uniform
// broadcast loads; *128 row scale folds into the address (IMAD.WIDE).
// Predicate-free 16-edge chunks + single padded tail (invalid slots gather
// the zero row). DEPTH-3 HADD2 tree folds all 8 edges per half in fp16
// before one fp32 convert+add per slot. fp32 accumulation across chunks.

#define FEAT 64
#define ROW_BYTES (FEAT * 2)
#define WARPS_PER_BLOCK 4
#define THREADS (WARPS_PER_BLOCK * 32)
#define NODES_PER_WARP 4
#define FULL 0xffffffffu

#define MAX_NODES 100000
__device__ __half g_norm_feat[(size_t)(MAX_NODES + 1) * FEAT];

__global__ __launch_bounds__(256) void scale_feat_kernel(
    const float* __restrict__ node_feat,
    const float* __restrict__ degrees,
    int n_nodes)
{
    const int i = blockIdx.x * blockDim.x + threadIdx.x;   // float4 index
    const int total = (n_nodes + 1) * (FEAT / 4);
    if (i >= total) return;
    const int node = i >> 4;
    __half2 h0, h1;
    if (node < n_nodes) {
        const float nd = rsqrtf(__ldg(&degrees[node]));
        float4 v = __ldg((const float4*)node_feat + i);
        h0 = __floats2half2_rn(v.x * nd, v.y * nd);
        h1 = __floats2half2_rn(v.z * nd, v.w * nd);
    } else {
        h0 = __floats2half2_rn(0.f, 0.f);
        h1 = h0;
    }
    __half2* dst = (__half2*)g_norm_feat + (size_t)i * 2;
    dst[0] = h0;
    dst[1] = h1;
}

// Gather+fold of 8 edges for one half-warp (16 total per warp call).
// Depth-3 fp16 tree: single fp32 convert+add per slot per call.
__device__ __forceinline__ void gather8(
    const char* __restrict__ base,
    int i0, int i1, int i2, int i3, int i4, int i5, int i6, int i7,
    float2& a0, float2& a1)
{
    const uint2 x0 = __ldg((const uint2*)(base + (size_t)i0 * ROW_BYTES));
    const uint2 x1 = __ldg((const uint2*)(base + (size_t)i1 * ROW_BYTES));
    const uint2 x2 = __ldg((const uint2*)(base + (size_t)i2 * ROW_BYTES));
    const uint2 x3 = __ldg((const uint2*)(base + (size_t)i3 * ROW_BYTES));
    const uint2 x4 = __ldg((const uint2*)(base + (size_t)i4 * ROW_BYTES));
    const uint2 x5 = __ldg((const uint2*)(base + (size_t)i5 * ROW_BYTES));
    const uint2 x6 = __ldg((const uint2*)(base + (size_t)i6 * ROW_BYTES));
    const uint2 x7 = __ldg((const uint2*)(base + (size_t)i7 * ROW_BYTES));

    {
        const __half2 t0 = __hadd2(*(const __half2*)&x0.x, *(const __half2*)&x1.x);
        const __half2 t1 = __hadd2(*(const __half2*)&x2.x, *(const __half2*)&x3.x);
        const __half2 t2 = __hadd2(*(const __half2*)&x4.x, *(const __half2*)&x5.x);
        const __half2 t3 = __hadd2(*(const __half2*)&x6.x, *(const __half2*)&x7.x);
        const __half2 u0 = __hadd2(t0, t1);
        const __half2 u1 = __hadd2(t2, t3);
        const float2 f = __half22float2(__hadd2(u0, u1));
        a0.x += f.x; a0.y += f.y;
    }
    {
        const __half2 t0 = __hadd2(*(const __half2*)&x0.y, *(const __half2*)&x1.y);
        const __half2 t1 = __hadd2(*(const __half2*)&x2.y, *(const __half2*)&x3.y);
        const __half2 t2 = __hadd2(*(const __half2*)&x4.y, *(const __half2*)&x5.y);
        const __half2 t3 = __hadd2(*(const __half2*)&x6.y, *(const __half2*)&x7.y);
        const __half2 u0 = __hadd2(t0, t1);
        const __half2 u1 = __hadd2(t2, t3);
        const float2 f = __half22float2(__hadd2(u0, u1));
        a1.x += f.x; a1.y += f.y;
    }
}

__global__ __launch_bounds__(THREADS) void gcn_agg_kernel(
    const int* __restrict__ row_ptr,
    const int* __restrict__ col_idx,
    float* __restrict__ out,
    int n_nodes)
{
    const int wid  = blockIdx.x * WARPS_PER_BLOCK + (threadIdx.x >> 5);
    const int lane = threadIdx.x & 31;
    const int half = lane >> 4;
    const int fl   = lane & 15;

    const int n0 = wid * NODES_PER_WARP;
    if (n0 >= n_nodes) return;

    // row_ptr[n0 .. n0+4] via lanes 0..4, broadcast by shfl.
    int rp_l = 0;
    if (lane <= NODES_PER_WARP) {
        int idx = n0 + lane;
        if (idx > n_nodes) idx = n_nodes;
        rp_l = __ldg(&row_ptr[idx]);
    }

    const char* __restrict__ base = (const char*)g_norm_feat + (size_t)fl * 8;

    #pragma unroll
    for (int j = 0; j < NODES_PER_WARP; ++j) {
        const int d = n0 + j;
        if (d >= n_nodes) break;
        const int s = __shfl_sync(FULL, rp_l, j);
        const int e = __shfl_sync(FULL, rp_l, j + 1);
        const int deg = e - s;

        float2 a0 = make_float2(0.f, 0.f);
        float2 a1 = make_float2(0.f, 0.f);

        // Predicate-free 16-edge chunks.
        int p = s;
        for (; p + 16 <= e; p += 16) {
            const int q = p + half;        // half h takes edges q, q+2, ...
            gather8(base,
                    __ldg(&col_idx[q]),      __ldg(&col_idx[q + 2]),
                    __ldg(&col_idx[q + 4]),  __ldg(&col_idx[q + 6]),
                    __ldg(&col_idx[q + 8]),  __ldg(&col_idx[q + 10]),
                    __ldg(&col_idx[q + 12]), __ldg(&col_idx[q + 14]),
                    a0, a1);
        }
        // Tail chunk (< 16 edges): invalid slots gather the zero row.
        if (p < e) {
            const int q = p + half;
            const int i0 = (q      < e) ? __ldg(&col_idx[q])      : MAX_NODES;
            const int i1 = (q + 2  < e) ? __ldg(&col_idx[q + 2])  : MAX_NODES;
            const int i2 = (q + 4  < e) ? __ldg(&col_idx[q + 4])  : MAX_NODES;
            const int i3 = (q + 6  < e) ? __ldg(&col_idx[q + 6])  : MAX_NODES;
            const int i4 = (q + 8  < e) ? __ldg(&col_idx[q + 8])  : MAX_NODES;
            const int i5 = (q + 10 < e) ? __ldg(&col_idx[q + 10]) : MAX_NODES;
            const int i6 = (q + 12 < e) ? __ldg(&col_idx[q + 12]) : MAX_NODES;
            const int i7 = (q + 14 < e) ? __ldg(&col_idx[q + 14]) : MAX_NODES;
            gather8(base, i0, i1, i2, i3, i4, i5, i6, i7, a0, a1);
        }

        // Fold the two half-warps (lanes with equal fl share feature slots).
        a0.x += __shfl_xor_sync(FULL, a0.x, 16);
        a0.y += __shfl_xor_sync(FULL, a0.y, 16);
        a1.x += __shfl_xor_sync(FULL, a1.x, 16);
        a1.y += __shfl_xor_sync(FULL, a1.y, 16);

        if (half == 0) {
            // degrees[d] == max(row_ptr[d+1]-row_ptr[d], 1) by construction.
            const float nd = rsqrtf(fmaxf((float)deg, 1.0f));
            float4 r;
            r.x = a0.x * nd;
            r.y = a0.y * nd;
            r.z = a1.x * nd;
            r.w = a1.y * nd;
            ((float4*)out)[(size_t)d * (FEAT / 4) + fl] = r;
        }
    }
}

// Full-precision fallback for oversize inputs.
__global__ __launch_bounds__(THREADS) void gcn_agg_fallback(
    const int* __restrict__ row_ptr,
    const int* __restrict__ col_idx,
    const float* __restrict__ node_feat,
    const float* __restrict__ degrees,
    float* __restrict__ out,
    int n_nodes)
{
    const int warp_id = blockIdx.x * WARPS_PER_BLOCK + (threadIdx.x >> 5);
    const int lane = threadIdx.x & 31;
    if (warp_id >= n_nodes) return;

    const int start = __ldg(&row_ptr[warp_id]);
    const int end   = __ldg(&row_ptr[warp_id + 1]);
    float2 acc = make_float2(0.f, 0.f);
    const float2* nf = (const float2*)node_feat;
    for (int e = start; e < end; ++e) {
        const int s = __ldg(&col_idx[e]);
        const float ns = rsqrtf(__ldg(&degrees[s]));
        const float2 v = __ldg(nf + (size_t)s * (FEAT / 2) + lane);
        acc.x = fmaf(ns, v.x, acc.x);
        acc.y = fmaf(ns, v.y, acc.y);
    }
    const float nd = rsqrtf(__ldg(&degrees[warp_id]));
    float2 r; r.x = acc.x * nd; r.y = acc.y * nd;
    ((float2*)out)[(size_t)warp_id * (FEAT / 2) + lane] = r;
}

extern "C" void kernel_launch(void* const* d_in, const int* in_sizes, int n_in,
                              void* d_out, int out_size)
{
    const int*   row_ptr   = (const int*)d_in[0];
    const int*   col_idx   = (const int*)d_in[1];
    const float* node_feat = (const float*)d_in[2];
    const float* degrees   = (const float*)d_in[3];
    float* out = (float*)d_out;

    const int n_nodes = in_sizes[0] - 1;

    if (n_nodes <= MAX_NODES) {
        const int total = (n_nodes + 1) * (FEAT / 4);
        scale_feat_kernel<<<(total + 255) / 256, 256>>>(node_feat, degrees, n_nodes);
        const int warps = (n_nodes + NODES_PER_WARP - 1) / NODES_PER_WARP;
        const int blocks = (warps + WARPS_PER_BLOCK - 1) / WARPS_PER_BLOCK;
        gcn_agg_kernel<<<blocks, THREADS>>>(row_ptr, col_idx, out, n_nodes);
    } else {
        const int blocks = (n_nodes + WARPS_PER_BLOCK - 1) / WARPS_PER_BLOCK;
        gcn_agg_fallback<<<blocks, THREADS>>>(row_ptr, col_idx, node_feat,
                                              degrees, out, n_nodes);
    }
}